// round 13
// baseline (speedup 1.0000x reference)
#include <cuda_runtime.h>
#include <cuda_fp16.h>
#include <math.h>
#include <stdint.h>

#define B_  2
#define S_  2048
#define D_  1024
#define H_  16
#define HD_ 64
#define M_  (B_*S_)   // 4096
#define LOG2E 1.4426950408889634f

// Scratch (allocation-free rule) — all fp16
__device__ __half g_Qh[B_*H_*S_*HD_];
__device__ __half g_Kh[B_*H_*S_*HD_];
__device__ __half g_Vh[B_*H_*HD_*S_];   // TRANSPOSED: [b,h,hd,s]
__device__ __half g_Ah[M_*D_];
__device__ __half g_xh[M_*D_];
__device__ __half g_wh[4*D_*D_];

__device__ __forceinline__ uint32_t h2u(__half2 h) { return *reinterpret_cast<uint32_t*>(&h); }

// D += A(16x16,row) * B(16x8,col)  fp16 inputs, fp32 accum
__device__ __forceinline__ void mma16(float d[4], const uint32_t a[4], const uint32_t b[2]) {
    asm volatile(
        "mma.sync.aligned.m16n8k16.row.col.f32.f16.f16.f32 "
        "{%0,%1,%2,%3}, {%4,%5,%6,%7}, {%8,%9}, {%0,%1,%2,%3};\n"
        : "+f"(d[0]), "+f"(d[1]), "+f"(d[2]), "+f"(d[3])
        : "r"(a[0]), "r"(a[1]), "r"(a[2]), "r"(a[3]), "r"(b[0]), "r"(b[1]));
}

__device__ __forceinline__ void cpa16(uint32_t dst, const void* src) {
    asm volatile("cp.async.cg.shared.global [%0], [%1], 16;" :: "r"(dst), "l"(src));
}
__device__ __forceinline__ void cp_commit() { asm volatile("cp.async.commit_group;"); }
template<int N> __device__ __forceinline__ void cp_wait() {
    asm volatile("cp.async.wait_group %0;" :: "n"(N));
}

// ---------------------------------------------------------------------------
// Pre-convert x and 4 weights to fp16 (rn)
// ---------------------------------------------------------------------------
__global__ __launch_bounds__(256) void precvt(const float* __restrict__ x,
                                              const float* __restrict__ Wq,
                                              const float* __restrict__ Wk,
                                              const float* __restrict__ Wv,
                                              const float* __restrict__ Wo)
{
    const int yy = blockIdx.y;
    const float* src; __half* dst; int n8;
    if (yy == 0)      { src = x;  dst = g_xh;           n8 = M_*D_/8; }
    else if (yy == 1) { src = Wq; dst = g_wh;           n8 = D_*D_/8; }
    else if (yy == 2) { src = Wk; dst = g_wh + 1*D_*D_; n8 = D_*D_/8; }
    else if (yy == 3) { src = Wv; dst = g_wh + 2*D_*D_; n8 = D_*D_/8; }
    else              { src = Wo; dst = g_wh + 3*D_*D_; n8 = D_*D_/8; }
#pragma unroll
    for (int it = 0; it < 2; it++) {
        int i = (blockIdx.x * 256 + threadIdx.x) + it * 256 * gridDim.x;
        if (i < n8) {
            float4 v0 = ((const float4*)src)[2*i];
            float4 v1 = ((const float4*)src)[2*i + 1];
            uint4 u;
            u.x = h2u(__floats2half2_rn(v0.x, v0.y));
            u.y = h2u(__floats2half2_rn(v0.z, v0.w));
            u.z = h2u(__floats2half2_rn(v1.x, v1.y));
            u.w = h2u(__floats2half2_rn(v1.z, v1.w));
            ((uint4*)dst)[i] = u;
        }
    }
}

// ---------------------------------------------------------------------------
// fp16 GEMM: 128x128 CTA, 256 thr (8 warps 4x2), warp 32x64, BK=32 halves,
// 3-STAGE cp.async pipeline, ONE __syncthreads per chunk.
// ---------------------------------------------------------------------------
#define BM 128
#define BN 128
#define BK 32
#define NCH (D_ / BK)                             // 32 chunks
#define SKB 144                                   // bytes per 32-half row
#define GBUF (BM * SKB)                           // 18432 B per buffer
#define GEMM_SMEM (6 * GBUF)                      // A0..A2, B0..B2 = 110,592 B

__device__ __forceinline__ void gemm_main(const __half* __restrict__ A,
                                          const __half* __restrict__ W,
                                          int m_base, int n_base,
                                          const char* smemc, uint32_t sm_u,
                                          float acc[2][8][4])
{
    const int tid  = threadIdx.x;
    const int lane = tid & 31;
    const int warp = tid >> 5;
    const int g  = lane >> 2;
    const int t4 = lane & 3;
    const int wm = warp & 3;
    const int wn = warp >> 2;

    auto stage = [&](int buf, int k0) {
#pragma unroll
        for (int it = 0; it < 2; it++) {
            int id = tid + it * 256;      // 512 16B chunks per operand
            int r  = id >> 2;
            int c  = id & 3;
            cpa16(sm_u + (uint32_t)(buf * GBUF + r * SKB + c * 16),
                  A + (size_t)(m_base + r) * D_ + k0 + c * 8);
            cpa16(sm_u + (uint32_t)(3 * GBUF + buf * GBUF + r * SKB + c * 16),
                  W + (size_t)(n_base + r) * D_ + k0 + c * 8);
        }
        cp_commit();
    };

    stage(0, 0);
    stage(1, BK);

#pragma unroll 1
    for (int ki = 0; ki < NCH; ki++) {
        if (ki == NCH - 1) cp_wait<0>(); else cp_wait<1>();
        __syncthreads();
        // stage chunk ki+2 into buffer (ki+2)%3 == (ki-1)%3 — the buffer all
        // warps finished reading before the barrier above.
        if (ki + 2 < NCH) stage((ki + 2) % 3, (ki + 2) * BK);

        const int cur = ki % 3;
        const char* Ac = smemc + cur * GBUF;
        const char* Bc = smemc + 3 * GBUF + cur * GBUF;
#pragma unroll
        for (int kk = 0; kk < 2; kk++) {       // two k16 groups per chunk
            uint32_t af[2][4];
#pragma unroll
            for (int ma = 0; ma < 2; ma++) {
                const char* rp = Ac + (wm * 32 + ma * 16 + g) * SKB + kk * 32 + 4 * t4;
                af[ma][0] = *(const uint32_t*)(rp);
                af[ma][1] = *(const uint32_t*)(rp + 8 * SKB);
                af[ma][2] = *(const uint32_t*)(rp + 16);
                af[ma][3] = *(const uint32_t*)(rp + 8 * SKB + 16);
            }
#pragma unroll
            for (int na = 0; na < 8; na++) {
                const char* cp = Bc + (wn * 64 + na * 8 + g) * SKB + kk * 32 + 4 * t4;
                uint32_t bf[2];
                bf[0] = *(const uint32_t*)(cp);
                bf[1] = *(const uint32_t*)(cp + 16);
                mma16(acc[0][na], af[0], bf);
                mma16(acc[1][na], af[1], bf);
            }
        }
    }
    __syncthreads();
}

// Fused QKV. Q scaled by 0.125*log2e; V stored transposed [b,h,hd,s].
__global__ __launch_bounds__(256, 2) void qkv_gemm()
{
    extern __shared__ __align__(16) char smc[];
    uint32_t sm_u = (uint32_t)__cvta_generic_to_shared(smc);

    const int wsel = blockIdx.y >> 3;
    const __half* W = g_wh + (size_t)wsel * D_ * D_;
    __half* Cout    = (wsel == 0) ? g_Qh : (wsel == 1) ? g_Kh : g_Vh;
    const float scale = (wsel == 0) ? (0.125f * LOG2E) : 1.0f;
    const int m_base = blockIdx.x * BM;
    const int n_base = (blockIdx.y & 7) * BN;

    float acc[2][8][4];
#pragma unroll
    for (int ma = 0; ma < 2; ma++)
#pragma unroll
        for (int na = 0; na < 8; na++)
#pragma unroll
            for (int i = 0; i < 4; i++) acc[ma][na][i] = 0.f;

    gemm_main(g_xh, W, m_base, n_base, smc, sm_u, acc);

    const int lane = threadIdx.x & 31, warp = threadIdx.x >> 5;
    const int g = lane >> 2, t4 = lane & 3;
    const int wm = warp & 3, wn = warp >> 2;
#pragma unroll
    for (int ma = 0; ma < 2; ma++)
#pragma unroll
        for (int na = 0; na < 8; na++) {
            int m0 = m_base + wm * 32 + ma * 16 + g;
            int n0 = n_base + wn * 64 + na * 8 + 2 * t4;
#pragma unroll
            for (int half_row = 0; half_row < 2; half_row++) {
                int m = m0 + half_row * 8;
                float v0 = acc[ma][na][half_row * 2 + 0] * scale;
                float v1 = acc[ma][na][half_row * 2 + 1] * scale;
                int b = m >> 11, s = m & 2047;
                int h = n0 >> 6, hd = n0 & 63;
                if (wsel == 2) {   // V transposed: [b,h,hd,s]
                    size_t base = ((size_t)(b * H_ + h) * HD_ + hd) * S_ + s;
                    g_Vh[base]      = __float2half_rn(v0);
                    g_Vh[base + S_] = __float2half_rn(v1);
                } else {
                    size_t idx = ((size_t)(b * H_ + h) * S_ + s) * HD_ + hd;
                    *(__half2*)&Cout[idx] = __floats2half2_rn(v0, v1);
                }
            }
        }
}

// Output projection: out = A @ Wo^T (fp32 output)
__global__ __launch_bounds__(256, 2) void out_gemm(float* __restrict__ out)
{
    extern __shared__ __align__(16) char smc[];
    uint32_t sm_u = (uint32_t)__cvta_generic_to_shared(smc);

    const int m_base = blockIdx.x * BM;
    const int n_base = blockIdx.y * BN;

    float acc[2][8][4];
#pragma unroll
    for (int ma = 0; ma < 2; ma++)
#pragma unroll
        for (int na = 0; na < 8; na++)
#pragma unroll
            for (int i = 0; i < 4; i++) acc[ma][na][i] = 0.f;

    gemm_main(g_Ah, g_wh + 3 * D_ * D_, m_base, n_base, smc, sm_u, acc);

    const int lane = threadIdx.x & 31, warp = threadIdx.x >> 5;
    const int g = lane >> 2, t4 = lane & 3;
    const int wm = warp & 3, wn = warp >> 2;
#pragma unroll
    for (int ma = 0; ma < 2; ma++)
#pragma unroll
        for (int na = 0; na < 8; na++) {
            int m0 = m_base + wm * 32 + ma * 16 + g;
            int n0 = n_base + wn * 64 + na * 8 + 2 * t4;
            *(float2*)&out[(size_t)m0 * D_ + n0]       = make_float2(acc[ma][na][0], acc[ma][na][1]);
            *(float2*)&out[(size_t)(m0 + 8) * D_ + n0] = make_float2(acc[ma][na][2], acc[ma][na][3]);
        }
}

// ---------------------------------------------------------------------------
// Flash attention, fp16 mma (body unchanged from round 12; occupancy 2 -> 3).
// smem: Qs 18432 + Ks 2x9216 + Vt 2x9216 = 55,296 B.
// ---------------------------------------------------------------------------
#define FSB 144
#define FOFF_K (128 * FSB)
#define FOFF_V (FOFF_K + 2 * 64 * FSB)
#define FLASH_SMEM (FOFF_V + 2 * 64 * FSB)   // 55,296 B

__global__ __launch_bounds__(128, 3) void flash_mma()
{
    extern __shared__ __align__(16) char fsc[];
    const uint32_t sm_u = (uint32_t)__cvta_generic_to_shared(fsc);

    const int t = (gridDim.x - 1) - blockIdx.x;   // heavy tiles first
    const int h = blockIdx.y;
    const int b = blockIdx.z;
    const int tid  = threadIdx.x;
    const int lane = tid & 31;
    const int w    = tid >> 5;
    const int g  = lane >> 2;
    const int t4 = lane & 3;

    const __half* Qp  = g_Qh + ((size_t)(b * H_ + h) * S_ + t * 128) * HD_;
    const __half* Kp  = g_Kh + ((size_t)(b * H_ + h) * S_) * HD_;
    const __half* Vtp = g_Vh + ((size_t)(b * H_ + h)) * HD_ * S_;   // [hd][s]

#pragma unroll
    for (int it = 0; it < 8; it++) {
        int f = tid + it * 128;
        int r = f >> 3, c = (f & 7) * 16;
        cpa16(sm_u + (uint32_t)(r * FSB + c), Qp + (size_t)r * HD_ + c / 2);
    }
#pragma unroll
    for (int it = 0; it < 4; it++) {
        int f = tid + it * 128;
        int r = f >> 3, c = (f & 7) * 16;
        cpa16(sm_u + (uint32_t)(FOFF_K + r * FSB + c), Kp + (size_t)r * HD_ + c / 2);
        cpa16(sm_u + (uint32_t)(FOFF_V + r * FSB + c), Vtp + (size_t)r * S_ + c / 2);
    }
    cp_commit();

    const float slope2 = exp2f(-0.5f * (float)(h + 1)) * LOG2E;
    int qr[2][2];
#pragma unroll
    for (int rb = 0; rb < 2; rb++) {
        qr[rb][0] = t * 128 + w * 32 + rb * 16 + g;
        qr[rb][1] = qr[rb][0] + 8;
    }

    float o[2][8][4];
    float mr[2][2], lr[2][2];
#pragma unroll
    for (int rb = 0; rb < 2; rb++) {
        mr[rb][0] = mr[rb][1] = -INFINITY;
        lr[rb][0] = lr[rb][1] = 0.f;
#pragma unroll
        for (int da = 0; da < 8; da++)
#pragma unroll
            for (int i = 0; i < 4; i++) o[rb][da][i] = 0.f;
    }

    const int j_end = t * 128 + 64;
    for (int j0 = 0; j0 <= j_end; j0 += 64) {
        const int cur = (j0 >> 6) & 1;
        if (j0 + 64 <= j_end) {
            const int nb = cur ^ 1;
#pragma unroll
            for (int it = 0; it < 4; it++) {
                int f = tid + it * 128;
                int r = f >> 3, c = (f & 7) * 16;
                cpa16(sm_u + (uint32_t)(FOFF_K + (nb * 64 + r) * FSB + c),
                      Kp + (size_t)(j0 + 64 + r) * HD_ + c / 2);
                cpa16(sm_u + (uint32_t)(FOFF_V + (nb * 64 + r) * FSB + c),
                      Vtp + (size_t)r * S_ + j0 + 64 + c / 2);
            }
            cp_commit();
            cp_wait<1>();
        } else {
            cp_wait<0>();
        }
        __syncthreads();

        const char* Kc = fsc + FOFF_K + cur * 64 * FSB;
        const char* Vc = fsc + FOFF_V + cur * 64 * FSB;

        // S = Q @ K^T : 4 k16-groups over HD=64
        float s[2][8][4];
#pragma unroll
        for (int rb = 0; rb < 2; rb++)
#pragma unroll
            for (int na = 0; na < 8; na++)
#pragma unroll
                for (int i = 0; i < 4; i++) s[rb][na][i] = 0.f;

#pragma unroll
        for (int kk = 0; kk < 4; kk++) {
            uint32_t aq[2][4];
#pragma unroll
            for (int rb = 0; rb < 2; rb++) {
                const char* rp = fsc + (w * 32 + rb * 16 + g) * FSB + kk * 32 + 4 * t4;
                aq[rb][0] = *(const uint32_t*)(rp);
                aq[rb][1] = *(const uint32_t*)(rp + 8 * FSB);
                aq[rb][2] = *(const uint32_t*)(rp + 16);
                aq[rb][3] = *(const uint32_t*)(rp + 8 * FSB + 16);
            }
#pragma unroll
            for (int na = 0; na < 8; na++) {
                const char* cp = Kc + (na * 8 + g) * FSB + kk * 32 + 4 * t4;
                uint32_t bf[2];
                bf[0] = *(const uint32_t*)(cp);
                bf[1] = *(const uint32_t*)(cp + 16);
                mma16(s[0][na], aq[0], bf);
                mma16(s[1][na], aq[1], bf);
            }
        }

        // ALiBi (base-2) + causal, per row-block
#pragma unroll
        for (int rb = 0; rb < 2; rb++) {
            const bool nm = (j0 + 63) > (t * 128 + w * 32 + rb * 16);
#pragma unroll
            for (int na = 0; na < 8; na++) {
                int jc = j0 + na * 8 + 2 * t4;
                s[rb][na][0] += slope2 * (float)(jc - qr[rb][0]);
                s[rb][na][1] += slope2 * (float)(jc + 1 - qr[rb][0]);
                s[rb][na][2] += slope2 * (float)(jc - qr[rb][1]);
                s[rb][na][3] += slope2 * (float)(jc + 1 - qr[rb][1]);
                if (nm) {
                    if (jc     > qr[rb][0]) s[rb][na][0] = -1e30f;
                    if (jc + 1 > qr[rb][0]) s[rb][na][1] = -1e30f;
                    if (jc     > qr[rb][1]) s[rb][na][2] = -1e30f;
                    if (jc + 1 > qr[rb][1]) s[rb][na][3] = -1e30f;
                }
            }
        }

        // online softmax (base-2); reduce over t4 lanes
#pragma unroll
        for (int rb = 0; rb < 2; rb++) {
            float mxA = -INFINITY, mxB = -INFINITY;
#pragma unroll
            for (int na = 0; na < 8; na++) {
                mxA = fmaxf(mxA, fmaxf(s[rb][na][0], s[rb][na][1]));
                mxB = fmaxf(mxB, fmaxf(s[rb][na][2], s[rb][na][3]));
            }
            mxA = fmaxf(mxA, __shfl_xor_sync(0xffffffffu, mxA, 1));
            mxA = fmaxf(mxA, __shfl_xor_sync(0xffffffffu, mxA, 2));
            mxB = fmaxf(mxB, __shfl_xor_sync(0xffffffffu, mxB, 1));
            mxB = fmaxf(mxB, __shfl_xor_sync(0xffffffffu, mxB, 2));

            float mnA = fmaxf(mr[rb][0], mxA), mnB = fmaxf(mr[rb][1], mxB);
            float aAl = exp2f(mr[rb][0] - mnA), aBl = exp2f(mr[rb][1] - mnB);
            mr[rb][0] = mnA; mr[rb][1] = mnB;

            float sumA = 0.f, sumB = 0.f;
#pragma unroll
            for (int na = 0; na < 8; na++) {
                s[rb][na][0] = exp2f(s[rb][na][0] - mnA);
                s[rb][na][1] = exp2f(s[rb][na][1] - mnA);
                s[rb][na][2] = exp2f(s[rb][na][2] - mnB);
                s[rb][na][3] = exp2f(s[rb][na][3] - mnB);
                sumA += s[rb][na][0] + s[rb][na][1];
                sumB += s[rb][na][2] + s[rb][na][3];
            }
            sumA += __shfl_xor_sync(0xffffffffu, sumA, 1);
            sumA += __shfl_xor_sync(0xffffffffu, sumA, 2);
            sumB += __shfl_xor_sync(0xffffffffu, sumB, 1);
            sumB += __shfl_xor_sync(0xffffffffu, sumB, 2);
            lr[rb][0] = lr[rb][0] * aAl + sumA;
            lr[rb][1] = lr[rb][1] * aBl + sumB;

#pragma unroll
            for (int da = 0; da < 8; da++) {
                o[rb][da][0] *= aAl; o[rb][da][1] *= aAl;
                o[rb][da][2] *= aBl; o[rb][da][3] *= aBl;
            }
        }

        // O += P @ V : 4 k16-groups over the 64 keys. A-frags from s regs.
#pragma unroll
        for (int kk = 0; kk < 4; kk++) {
            uint32_t ap[2][4];
#pragma unroll
            for (int rb = 0; rb < 2; rb++) {
                ap[rb][0] = h2u(__floats2half2_rn(s[rb][2*kk][0],   s[rb][2*kk][1]));
                ap[rb][1] = h2u(__floats2half2_rn(s[rb][2*kk][2],   s[rb][2*kk][3]));
                ap[rb][2] = h2u(__floats2half2_rn(s[rb][2*kk+1][0], s[rb][2*kk+1][1]));
                ap[rb][3] = h2u(__floats2half2_rn(s[rb][2*kk+1][2], s[rb][2*kk+1][3]));
            }
#pragma unroll
            for (int da = 0; da < 8; da++) {
                const char* cp = Vc + (da * 8 + g) * FSB + kk * 32 + 4 * t4;
                uint32_t bf[2];
                bf[0] = *(const uint32_t*)(cp);
                bf[1] = *(const uint32_t*)(cp + 16);
                mma16(o[0][da], ap[0], bf);
                mma16(o[1][da], ap[1], bf);
            }
        }
        __syncthreads();
    }

    // normalize + write [B,S,D] as fp16 (input to out_gemm)
#pragma unroll
    for (int rb = 0; rb < 2; rb++) {
        const float invA = 1.0f / lr[rb][0], invB = 1.0f / lr[rb][1];
#pragma unroll
        for (int da = 0; da < 8; da++) {
            int col = h * 64 + da * 8 + 2 * t4;
            size_t rA = ((size_t)b * S_ + qr[rb][0]) * D_ + col;
            size_t rB = ((size_t)b * S_ + qr[rb][1]) * D_ + col;
            *(__half2*)&g_Ah[rA] = __floats2half2_rn(o[rb][da][0] * invA, o[rb][da][1] * invA);
            *(__half2*)&g_Ah[rB] = __floats2half2_rn(o[rb][da][2] * invB, o[rb][da][3] * invB);
        }
    }
}

// ---------------------------------------------------------------------------
extern "C" void kernel_launch(void* const* d_in, const int* in_sizes, int n_in,
                              void* d_out, int out_size)
{
    const float* x  = (const float*)d_in[0];
    // d_in[1] = causal mask, applied analytically
    const float* Wq = (const float*)d_in[2];
    const float* Wk = (const float*)d_in[3];
    const float* Wv = (const float*)d_in[4];
    const float* Wo = (const float*)d_in[5];
    float* out = (float*)d_out;

    cudaFuncSetAttribute(qkv_gemm, cudaFuncAttributeMaxDynamicSharedMemorySize, (int)GEMM_SMEM);
    cudaFuncSetAttribute(out_gemm, cudaFuncAttributeMaxDynamicSharedMemorySize, (int)GEMM_SMEM);
    cudaFuncSetAttribute(flash_mma, cudaFuncAttributeMaxDynamicSharedMemorySize, (int)FLASH_SMEM);

    dim3 g0(1024, 5);
    precvt<<<g0, 256>>>(x, Wq, Wk, Wv, Wo);

    dim3 g1(M_ / BM, 24);                 // 3 weights x 8 n-tiles
    qkv_gemm<<<g1, 256, GEMM_SMEM>>>();

    dim3 g2(S_ / 128, H_, B_);
    flash_mma<<<g2, 128, FLASH_SMEM>>>();

    dim3 g3(M_ / BM, D_ / BN);
    out_gemm<<<g3, 256, GEMM_SMEM>>>(out);
}

// round 15
// speedup vs baseline: 1.0908x; 1.0908x over previous
#include <cuda_runtime.h>
#include <cuda_fp16.h>
#include <math.h>
#include <stdint.h>

#define B_  2
#define S_  2048
#define D_  1024
#define H_  16
#define HD_ 64
#define M_  (B_*S_)   // 4096
#define LOG2E 1.4426950408889634f

// Scratch (allocation-free rule) — all fp16
__device__ __half g_Qh[B_*H_*S_*HD_];
__device__ __half g_Kh[B_*H_*S_*HD_];
__device__ __half g_Vh[B_*H_*HD_*S_];   // TRANSPOSED: [b,h,hd,s]
__device__ __half g_Ah[M_*D_];
__device__ __half g_xh[M_*D_];
__device__ __half g_wh[4*D_*D_];

__device__ __forceinline__ uint32_t h2u(__half2 h) { return *reinterpret_cast<uint32_t*>(&h); }

// D += A(16x16,row) * B(16x8,col)  fp16 inputs, fp32 accum
__device__ __forceinline__ void mma16(float d[4], const uint32_t a[4], const uint32_t b[2]) {
    asm volatile(
        "mma.sync.aligned.m16n8k16.row.col.f32.f16.f16.f32 "
        "{%0,%1,%2,%3}, {%4,%5,%6,%7}, {%8,%9}, {%0,%1,%2,%3};\n"
        : "+f"(d[0]), "+f"(d[1]), "+f"(d[2]), "+f"(d[3])
        : "r"(a[0]), "r"(a[1]), "r"(a[2]), "r"(a[3]), "r"(b[0]), "r"(b[1]));
}

// ldmatrix x4: four 8x8 b16 matrices -> r0..r3 (reg i = matrix i frag)
__device__ __forceinline__ void ldsm4(uint32_t& r0, uint32_t& r1, uint32_t& r2, uint32_t& r3,
                                      uint32_t addr) {
    asm volatile("ldmatrix.sync.aligned.m8n8.x4.shared.b16 {%0,%1,%2,%3}, [%4];"
                 : "=r"(r0), "=r"(r1), "=r"(r2), "=r"(r3) : "r"(addr));
}

__device__ __forceinline__ void cpa16(uint32_t dst, const void* src) {
    asm volatile("cp.async.cg.shared.global [%0], [%1], 16;" :: "r"(dst), "l"(src));
}
__device__ __forceinline__ void cp_commit() { asm volatile("cp.async.commit_group;"); }
template<int N> __device__ __forceinline__ void cp_wait() {
    asm volatile("cp.async.wait_group %0;" :: "n"(N));
}

// ---------------------------------------------------------------------------
// Pre-convert x and 4 weights to fp16 (rn)
// ---------------------------------------------------------------------------
__global__ __launch_bounds__(256) void precvt(const float* __restrict__ x,
                                              const float* __restrict__ Wq,
                                              const float* __restrict__ Wk,
                                              const float* __restrict__ Wv,
                                              const float* __restrict__ Wo)
{
    const int yy = blockIdx.y;
    const float* src; __half* dst; int n8;
    if (yy == 0)      { src = x;  dst = g_xh;           n8 = M_*D_/8; }
    else if (yy == 1) { src = Wq; dst = g_wh;           n8 = D_*D_/8; }
    else if (yy == 2) { src = Wk; dst = g_wh + 1*D_*D_; n8 = D_*D_/8; }
    else if (yy == 3) { src = Wv; dst = g_wh + 2*D_*D_; n8 = D_*D_/8; }
    else              { src = Wo; dst = g_wh + 3*D_*D_; n8 = D_*D_/8; }
#pragma unroll
    for (int it = 0; it < 2; it++) {
        int i = (blockIdx.x * 256 + threadIdx.x) + it * 256 * gridDim.x;
        if (i < n8) {
            float4 v0 = ((const float4*)src)[2*i];
            float4 v1 = ((const float4*)src)[2*i + 1];
            uint4 u;
            u.x = h2u(__floats2half2_rn(v0.x, v0.y));
            u.y = h2u(__floats2half2_rn(v0.z, v0.w));
            u.z = h2u(__floats2half2_rn(v1.x, v1.y));
            u.w = h2u(__floats2half2_rn(v1.z, v1.w));
            ((uint4*)dst)[i] = u;
        }
    }
}

// ---------------------------------------------------------------------------
// fp16 GEMM: 128x128 CTA, 256 thr (8 warps 4x2), warp 32x64, BK=32 halves,
// cp.async double-buffered, ldmatrix.x4 fragment loads.
// ---------------------------------------------------------------------------
#define BM 128
#define BN 128
#define BK 32
#define SKB 144                                   // bytes per 32-half row
#define GBUF (BM * SKB)                           // 18432 B per buffer
#define GEMM_SMEM (4 * GBUF)                      // A0,A1,B0,B1 = 73,728 B

__device__ __forceinline__ void gemm_main(const __half* __restrict__ A,
                                          const __half* __restrict__ W,
                                          int m_base, int n_base,
                                          uint32_t sm_u,
                                          float acc[2][8][4])
{
    const int tid  = threadIdx.x;
    const int lane = tid & 31;
    const int warp = tid >> 5;
    const int wm = warp & 3;
    const int wn = warp >> 2;

    // ldmatrix lane->address components (A-pattern and B-pattern)
    const int a_row = (lane & 7) + ((lane >> 3) & 1) * 8;   // + tile base
    const int a_col = ((lane >> 4) & 1) * 16;               // + kk*32
    const int b_row = (lane & 7) + ((lane >> 4) & 1) * 8;
    const int b_col = ((lane >> 3) & 1) * 16;

    auto stage = [&](int buf, int k0) {
#pragma unroll
        for (int it = 0; it < 2; it++) {
            int id = tid + it * 256;      // 512 16B chunks per operand
            int r  = id >> 2;
            int c  = id & 3;
            cpa16(sm_u + (uint32_t)(buf * GBUF + r * SKB + c * 16),
                  A + (size_t)(m_base + r) * D_ + k0 + c * 8);
            cpa16(sm_u + (uint32_t)(2 * GBUF + buf * GBUF + r * SKB + c * 16),
                  W + (size_t)(n_base + r) * D_ + k0 + c * 8);
        }
    };

    stage(0, 0);
    cp_commit();

    for (int ki = 0; ki < D_ / BK; ki++) {
        const int cur = ki & 1;
        if (ki + 1 < D_ / BK) {
            stage(cur ^ 1, (ki + 1) * BK);
            cp_commit();
            cp_wait<1>();
        } else {
            cp_wait<0>();
        }
        __syncthreads();

        const uint32_t Au = sm_u + (uint32_t)(cur * GBUF);
        const uint32_t Bu = sm_u + (uint32_t)(2 * GBUF + cur * GBUF);
#pragma unroll
        for (int kk = 0; kk < 2; kk++) {       // two k16 groups per chunk
            uint32_t af[2][4];
#pragma unroll
            for (int ma = 0; ma < 2; ma++)
                ldsm4(af[ma][0], af[ma][1], af[ma][2], af[ma][3],
                      Au + (uint32_t)((wm * 32 + ma * 16 + a_row) * SKB + a_col + kk * 32));
#pragma unroll
            for (int np = 0; np < 4; np++) {
                uint32_t b4[4];
                ldsm4(b4[0], b4[1], b4[2], b4[3],
                      Bu + (uint32_t)((wn * 64 + np * 16 + b_row) * SKB + b_col + kk * 32));
                uint32_t bf0[2] = { b4[0], b4[1] };
                uint32_t bf1[2] = { b4[2], b4[3] };
                mma16(acc[0][2 * np],     af[0], bf0);
                mma16(acc[1][2 * np],     af[1], bf0);
                mma16(acc[0][2 * np + 1], af[0], bf1);
                mma16(acc[1][2 * np + 1], af[1], bf1);
            }
        }
        __syncthreads();
    }
}

// Fused QKV. Q scaled by 0.125*log2e; V stored transposed [b,h,hd,s].
__global__ __launch_bounds__(256, 2) void qkv_gemm()
{
    extern __shared__ __align__(16) char smc[];
    uint32_t sm_u = (uint32_t)__cvta_generic_to_shared(smc);

    const int wsel = blockIdx.y >> 3;
    const __half* W = g_wh + (size_t)wsel * D_ * D_;
    __half* Cout    = (wsel == 0) ? g_Qh : (wsel == 1) ? g_Kh : g_Vh;
    const float scale = (wsel == 0) ? (0.125f * LOG2E) : 1.0f;
    const int m_base = blockIdx.x * BM;
    const int n_base = (blockIdx.y & 7) * BN;

    float acc[2][8][4];
#pragma unroll
    for (int ma = 0; ma < 2; ma++)
#pragma unroll
        for (int na = 0; na < 8; na++)
#pragma unroll
            for (int i = 0; i < 4; i++) acc[ma][na][i] = 0.f;

    gemm_main(g_xh, W, m_base, n_base, sm_u, acc);

    const int lane = threadIdx.x & 31, warp = threadIdx.x >> 5;
    const int g = lane >> 2, t4 = lane & 3;
    const int wm = warp & 3, wn = warp >> 2;
#pragma unroll
    for (int ma = 0; ma < 2; ma++)
#pragma unroll
        for (int na = 0; na < 8; na++) {
            int m0 = m_base + wm * 32 + ma * 16 + g;
            int n0 = n_base + wn * 64 + na * 8 + 2 * t4;
#pragma unroll
            for (int half_row = 0; half_row < 2; half_row++) {
                int m = m0 + half_row * 8;
                float v0 = acc[ma][na][half_row * 2 + 0] * scale;
                float v1 = acc[ma][na][half_row * 2 + 1] * scale;
                int b = m >> 11, s = m & 2047;
                int h = n0 >> 6, hd = n0 & 63;
                if (wsel == 2) {   // V transposed: [b,h,hd,s]
                    size_t base = ((size_t)(b * H_ + h) * HD_ + hd) * S_ + s;
                    g_Vh[base]      = __float2half_rn(v0);
                    g_Vh[base + S_] = __float2half_rn(v1);
                } else {
                    size_t idx = ((size_t)(b * H_ + h) * S_ + s) * HD_ + hd;
                    *(__half2*)&Cout[idx] = __floats2half2_rn(v0, v1);
                }
            }
        }
}

// Output projection: out = A @ Wo^T (fp32 output)
__global__ __launch_bounds__(256, 2) void out_gemm(float* __restrict__ out)
{
    extern __shared__ __align__(16) char smc[];
    uint32_t sm_u = (uint32_t)__cvta_generic_to_shared(smc);

    const int m_base = blockIdx.x * BM;
    const int n_base = blockIdx.y * BN;

    float acc[2][8][4];
#pragma unroll
    for (int ma = 0; ma < 2; ma++)
#pragma unroll
        for (int na = 0; na < 8; na++)
#pragma unroll
            for (int i = 0; i < 4; i++) acc[ma][na][i] = 0.f;

    gemm_main(g_Ah, g_wh + 3 * D_ * D_, m_base, n_base, sm_u, acc);

    const int lane = threadIdx.x & 31, warp = threadIdx.x >> 5;
    const int g = lane >> 2, t4 = lane & 3;
    const int wm = warp & 3, wn = warp >> 2;
#pragma unroll
    for (int ma = 0; ma < 2; ma++)
#pragma unroll
        for (int na = 0; na < 8; na++) {
            int m0 = m_base + wm * 32 + ma * 16 + g;
            int n0 = n_base + wn * 64 + na * 8 + 2 * t4;
            *(float2*)&out[(size_t)m0 * D_ + n0]       = make_float2(acc[ma][na][0], acc[ma][na][1]);
            *(float2*)&out[(size_t)(m0 + 8) * D_ + n0] = make_float2(acc[ma][na][2], acc[ma][na][3]);
        }
}

// ---------------------------------------------------------------------------
// Flash attention, fp16 mma + ldmatrix. CTA = (b,h,128-q-tile), 128 thr /
// 4 warps, warp = 32 q-rows (two 16-row blocks). Double-buffered cp.async,
// V transposed. PV A-frags packed straight from softmax registers.
// smem: Qs 18432 + Ks 2x9216 + Vt 2x9216 = 55,296 B.
// ---------------------------------------------------------------------------
#define FSB 144
#define FOFF_K (128 * FSB)
#define FOFF_V (FOFF_K + 2 * 64 * FSB)
#define FLASH_SMEM (FOFF_V + 2 * 64 * FSB)   // 55,296 B

__global__ __launch_bounds__(128, 2) void flash_mma()
{
    extern __shared__ __align__(16) char fsc[];
    const uint32_t sm_u = (uint32_t)__cvta_generic_to_shared(fsc);

    const int t = (gridDim.x - 1) - blockIdx.x;   // heavy tiles first
    const int h = blockIdx.y;
    const int b = blockIdx.z;
    const int tid  = threadIdx.x;
    const int lane = tid & 31;
    const int w    = tid >> 5;
    const int g  = lane >> 2;
    const int t4 = lane & 3;

    const int a_row = (lane & 7) + ((lane >> 3) & 1) * 8;
    const int a_col = ((lane >> 4) & 1) * 16;
    const int b_row = (lane & 7) + ((lane >> 4) & 1) * 8;
    const int b_col = ((lane >> 3) & 1) * 16;

    const __half* Qp  = g_Qh + ((size_t)(b * H_ + h) * S_ + t * 128) * HD_;
    const __half* Kp  = g_Kh + ((size_t)(b * H_ + h) * S_) * HD_;
    const __half* Vtp = g_Vh + ((size_t)(b * H_ + h)) * HD_ * S_;   // [hd][s]

    // stage Q: 128 rows x 8 chunks = 1024, 128 thr -> 8 iters
#pragma unroll
    for (int it = 0; it < 8; it++) {
        int f = tid + it * 128;
        int r = f >> 3, c = (f & 7) * 16;
        cpa16(sm_u + (uint32_t)(r * FSB + c), Qp + (size_t)r * HD_ + c / 2);
    }
    // stage K0 / Vt0: 64 rows x 8 chunks = 512 each -> 4 iters
#pragma unroll
    for (int it = 0; it < 4; it++) {
        int f = tid + it * 128;
        int r = f >> 3, c = (f & 7) * 16;
        cpa16(sm_u + (uint32_t)(FOFF_K + r * FSB + c), Kp + (size_t)r * HD_ + c / 2);
        cpa16(sm_u + (uint32_t)(FOFF_V + r * FSB + c), Vtp + (size_t)r * S_ + c / 2);
    }
    cp_commit();

    const float slope2 = exp2f(-0.5f * (float)(h + 1)) * LOG2E;
    int qr[2][2];
#pragma unroll
    for (int rb = 0; rb < 2; rb++) {
        qr[rb][0] = t * 128 + w * 32 + rb * 16 + g;
        qr[rb][1] = qr[rb][0] + 8;
    }

    float o[2][8][4];
    float mr[2][2], lr[2][2];
#pragma unroll
    for (int rb = 0; rb < 2; rb++) {
        mr[rb][0] = mr[rb][1] = -INFINITY;
        lr[rb][0] = lr[rb][1] = 0.f;
#pragma unroll
        for (int da = 0; da < 8; da++)
#pragma unroll
            for (int i = 0; i < 4; i++) o[rb][da][i] = 0.f;
    }

    const int j_end = t * 128 + 64;
    for (int j0 = 0; j0 <= j_end; j0 += 64) {
        const int cur = (j0 >> 6) & 1;
        if (j0 + 64 <= j_end) {
            const int nb = cur ^ 1;
#pragma unroll
            for (int it = 0; it < 4; it++) {
                int f = tid + it * 128;
                int r = f >> 3, c = (f & 7) * 16;
                cpa16(sm_u + (uint32_t)(FOFF_K + (nb * 64 + r) * FSB + c),
                      Kp + (size_t)(j0 + 64 + r) * HD_ + c / 2);
                cpa16(sm_u + (uint32_t)(FOFF_V + (nb * 64 + r) * FSB + c),
                      Vtp + (size_t)r * S_ + j0 + 64 + c / 2);
            }
            cp_commit();
            cp_wait<1>();
        } else {
            cp_wait<0>();
        }
        __syncthreads();

        const uint32_t Ku = sm_u + (uint32_t)(FOFF_K + cur * 64 * FSB);
        const uint32_t Vu = sm_u + (uint32_t)(FOFF_V + cur * 64 * FSB);

        // S = Q @ K^T : 4 k16-groups over HD=64
        float s[2][8][4];
#pragma unroll
        for (int rb = 0; rb < 2; rb++)
#pragma unroll
            for (int na = 0; na < 8; na++)
#pragma unroll
                for (int i = 0; i < 4; i++) s[rb][na][i] = 0.f;

#pragma unroll
        for (int kk = 0; kk < 4; kk++) {
            uint32_t aq[2][4];
#pragma unroll
            for (int rb = 0; rb < 2; rb++)
                ldsm4(aq[rb][0], aq[rb][1], aq[rb][2], aq[rb][3],
                      sm_u + (uint32_t)((w * 32 + rb * 16 + a_row) * FSB + a_col + kk * 32));
#pragma unroll
            for (int np = 0; np < 4; np++) {
                uint32_t b4[4];
                ldsm4(b4[0], b4[1], b4[2], b4[3],
                      Ku + (uint32_t)((np * 16 + b_row) * FSB + b_col + kk * 32));
                uint32_t bf0[2] = { b4[0], b4[1] };
                uint32_t bf1[2] = { b4[2], b4[3] };
                mma16(s[0][2 * np],     aq[0], bf0);
                mma16(s[1][2 * np],     aq[1], bf0);
                mma16(s[0][2 * np + 1], aq[0], bf1);
                mma16(s[1][2 * np + 1], aq[1], bf1);
            }
        }

        // ALiBi (base-2) + causal, per row-block
#pragma unroll
        for (int rb = 0; rb < 2; rb++) {
            const bool nm = (j0 + 63) > (t * 128 + w * 32 + rb * 16);
#pragma unroll
            for (int na = 0; na < 8; na++) {
                int jc = j0 + na * 8 + 2 * t4;
                s[rb][na][0] += slope2 * (float)(jc - qr[rb][0]);
                s[rb][na][1] += slope2 * (float)(jc + 1 - qr[rb][0]);
                s[rb][na][2] += slope2 * (float)(jc - qr[rb][1]);
                s[rb][na][3] += slope2 * (float)(jc + 1 - qr[rb][1]);
                if (nm) {
                    if (jc     > qr[rb][0]) s[rb][na][0] = -1e30f;
                    if (jc + 1 > qr[rb][0]) s[rb][na][1] = -1e30f;
                    if (jc     > qr[rb][1]) s[rb][na][2] = -1e30f;
                    if (jc + 1 > qr[rb][1]) s[rb][na][3] = -1e30f;
                }
            }
        }

        // online softmax (base-2); reduce over t4 lanes
#pragma unroll
        for (int rb = 0; rb < 2; rb++) {
            float mxA = -INFINITY, mxB = -INFINITY;
#pragma unroll
            for (int na = 0; na < 8; na++) {
                mxA = fmaxf(mxA, fmaxf(s[rb][na][0], s[rb][na][1]));
                mxB = fmaxf(mxB, fmaxf(s[rb][na][2], s[rb][na][3]));
            }
            mxA = fmaxf(mxA, __shfl_xor_sync(0xffffffffu, mxA, 1));
            mxA = fmaxf(mxA, __shfl_xor_sync(0xffffffffu, mxA, 2));
            mxB = fmaxf(mxB, __shfl_xor_sync(0xffffffffu, mxB, 1));
            mxB = fmaxf(mxB, __shfl_xor_sync(0xffffffffu, mxB, 2));

            float mnA = fmaxf(mr[rb][0], mxA), mnB = fmaxf(mr[rb][1], mxB);
            float aAl = exp2f(mr[rb][0] - mnA), aBl = exp2f(mr[rb][1] - mnB);
            mr[rb][0] = mnA; mr[rb][1] = mnB;

            float sumA = 0.f, sumB = 0.f;
#pragma unroll
            for (int na = 0; na < 8; na++) {
                s[rb][na][0] = exp2f(s[rb][na][0] - mnA);
                s[rb][na][1] = exp2f(s[rb][na][1] - mnA);
                s[rb][na][2] = exp2f(s[rb][na][2] - mnB);
                s[rb][na][3] = exp2f(s[rb][na][3] - mnB);
                sumA += s[rb][na][0] + s[rb][na][1];
                sumB += s[rb][na][2] + s[rb][na][3];
            }
            sumA += __shfl_xor_sync(0xffffffffu, sumA, 1);
            sumA += __shfl_xor_sync(0xffffffffu, sumA, 2);
            sumB += __shfl_xor_sync(0xffffffffu, sumB, 1);
            sumB += __shfl_xor_sync(0xffffffffu, sumB, 2);
            lr[rb][0] = lr[rb][0] * aAl + sumA;
            lr[rb][1] = lr[rb][1] * aBl + sumB;

#pragma unroll
            for (int da = 0; da < 8; da++) {
                o[rb][da][0] *= aAl; o[rb][da][1] *= aAl;
                o[rb][da][2] *= aBl; o[rb][da][3] *= aBl;
            }
        }

        // O += P @ V : 4 k16-groups over the 64 keys. A-frags from s regs.
#pragma unroll
        for (int kk = 0; kk < 4; kk++) {
            uint32_t ap[2][4];
#pragma unroll
            for (int rb = 0; rb < 2; rb++) {
                ap[rb][0] = h2u(__floats2half2_rn(s[rb][2*kk][0],   s[rb][2*kk][1]));
                ap[rb][1] = h2u(__floats2half2_rn(s[rb][2*kk][2],   s[rb][2*kk][3]));
                ap[rb][2] = h2u(__floats2half2_rn(s[rb][2*kk+1][0], s[rb][2*kk+1][1]));
                ap[rb][3] = h2u(__floats2half2_rn(s[rb][2*kk+1][2], s[rb][2*kk+1][3]));
            }
#pragma unroll
            for (int np = 0; np < 4; np++) {
                uint32_t b4[4];
                ldsm4(b4[0], b4[1], b4[2], b4[3],
                      Vu + (uint32_t)((np * 16 + b_row) * FSB + b_col + kk * 32));
                uint32_t bf0[2] = { b4[0], b4[1] };
                uint32_t bf1[2] = { b4[2], b4[3] };
                mma16(o[0][2 * np],     ap[0], bf0);
                mma16(o[1][2 * np],     ap[1], bf0);
                mma16(o[0][2 * np + 1], ap[0], bf1);
                mma16(o[1][2 * np + 1], ap[1], bf1);
            }
        }
        __syncthreads();
    }

    // normalize + write [B,S,D] as fp16 (input to out_gemm)
#pragma unroll
    for (int rb = 0; rb < 2; rb++) {
        const float invA = 1.0f / lr[rb][0], invB = 1.0f / lr[rb][1];
#pragma unroll
        for (int da = 0; da < 8; da++) {
            int col = h * 64 + da * 8 + 2 * t4;
            size_t rA = ((size_t)b * S_ + qr[rb][0]) * D_ + col;
            size_t rB = ((size_t)b * S_ + qr[rb][1]) * D_ + col;
            *(__half2*)&g_Ah[rA] = __floats2half2_rn(o[rb][da][0] * invA, o[rb][da][1] * invA);
            *(__half2*)&g_Ah[rB] = __floats2half2_rn(o[rb][da][2] * invB, o[rb][da][3] * invB);
        }
    }
}

// ---------------------------------------------------------------------------
extern "C" void kernel_launch(void* const* d_in, const int* in_sizes, int n_in,
                              void* d_out, int out_size)
{
    const float* x  = (const float*)d_in[0];
    // d_in[1] = causal mask, applied analytically
    const float* Wq = (const float*)d_in[2];
    const float* Wk = (const float*)d_in[3];
    const float* Wv = (const float*)d_in[4];
    const float* Wo = (const float*)d_in[5];
    float* out = (float*)d_out;

    cudaFuncSetAttribute(qkv_gemm, cudaFuncAttributeMaxDynamicSharedMemorySize, (int)GEMM_SMEM);
    cudaFuncSetAttribute(out_gemm, cudaFuncAttributeMaxDynamicSharedMemorySize, (int)GEMM_SMEM);
    cudaFuncSetAttribute(flash_mma, cudaFuncAttributeMaxDynamicSharedMemorySize, (int)FLASH_SMEM);

    dim3 g0(1024, 5);
    precvt<<<g0, 256>>>(x, Wq, Wk, Wv, Wo);

    dim3 g1(M_ / BM, 24);                 // 3 weights x 8 n-tiles
    qkv_gemm<<<g1, 256, GEMM_SMEM>>>();

    dim3 g2(S_ / 128, H_, B_);
    flash_mma<<<g2, 128, FLASH_SMEM>>>();

    dim3 g3(M_ / BM, D_ / BN);
    out_gemm<<<g3, 256, GEMM_SMEM>>>(out);
}

// round 16
// speedup vs baseline: 1.1629x; 1.0661x over previous
#include <cuda_runtime.h>
#include <cuda_fp16.h>
#include <math.h>
#include <stdint.h>

#define B_  2
#define S_  2048
#define D_  1024
#define H_  16
#define HD_ 64
#define M_  (B_*S_)   // 4096
#define LOG2E 1.4426950408889634f

// Scratch (allocation-free rule) — all fp16
__device__ __half g_Qh[B_*H_*S_*HD_];
__device__ __half g_Kh[B_*H_*S_*HD_];
__device__ __half g_Vh[B_*H_*HD_*S_];   // TRANSPOSED: [b,h,hd,s]
__device__ __half g_Ah[M_*D_];
__device__ __half g_xh[M_*D_];
__device__ __half g_wh[4*D_*D_];

__device__ __forceinline__ uint32_t h2u(__half2 h) { return *reinterpret_cast<uint32_t*>(&h); }

// D += A(16x16,row) * B(16x8,col)  fp16 inputs, fp32 accum
__device__ __forceinline__ void mma16(float d[4], const uint32_t a[4], const uint32_t b[2]) {
    asm volatile(
        "mma.sync.aligned.m16n8k16.row.col.f32.f16.f16.f32 "
        "{%0,%1,%2,%3}, {%4,%5,%6,%7}, {%8,%9}, {%0,%1,%2,%3};\n"
        : "+f"(d[0]), "+f"(d[1]), "+f"(d[2]), "+f"(d[3])
        : "r"(a[0]), "r"(a[1]), "r"(a[2]), "r"(a[3]), "r"(b[0]), "r"(b[1]));
}

// ldmatrix x4: four 8x8 b16 matrices -> r0..r3
__device__ __forceinline__ void ldsm4(uint32_t& r0, uint32_t& r1, uint32_t& r2, uint32_t& r3,
                                      uint32_t addr) {
    asm volatile("ldmatrix.sync.aligned.m8n8.x4.shared.b16 {%0,%1,%2,%3}, [%4];"
                 : "=r"(r0), "=r"(r1), "=r"(r2), "=r"(r3) : "r"(addr));
}

__device__ __forceinline__ void cpa16(uint32_t dst, const void* src) {
    asm volatile("cp.async.cg.shared.global [%0], [%1], 16;" :: "r"(dst), "l"(src));
}
__device__ __forceinline__ void cp_commit() { asm volatile("cp.async.commit_group;"); }
template<int N> __device__ __forceinline__ void cp_wait() {
    asm volatile("cp.async.wait_group %0;" :: "n"(N));
}

// ---------------------------------------------------------------------------
// Pre-convert x and 4 weights to fp16 (rn)
// ---------------------------------------------------------------------------
__global__ __launch_bounds__(256) void precvt(const float* __restrict__ x,
                                              const float* __restrict__ Wq,
                                              const float* __restrict__ Wk,
                                              const float* __restrict__ Wv,
                                              const float* __restrict__ Wo)
{
    const int yy = blockIdx.y;
    const float* src; __half* dst; int n8;
    if (yy == 0)      { src = x;  dst = g_xh;           n8 = M_*D_/8; }
    else if (yy == 1) { src = Wq; dst = g_wh;           n8 = D_*D_/8; }
    else if (yy == 2) { src = Wk; dst = g_wh + 1*D_*D_; n8 = D_*D_/8; }
    else if (yy == 3) { src = Wv; dst = g_wh + 2*D_*D_; n8 = D_*D_/8; }
    else              { src = Wo; dst = g_wh + 3*D_*D_; n8 = D_*D_/8; }
#pragma unroll
    for (int it = 0; it < 2; it++) {
        int i = (blockIdx.x * 256 + threadIdx.x) + it * 256 * gridDim.x;
        if (i < n8) {
            float4 v0 = ((const float4*)src)[2*i];
            float4 v1 = ((const float4*)src)[2*i + 1];
            uint4 u;
            u.x = h2u(__floats2half2_rn(v0.x, v0.y));
            u.y = h2u(__floats2half2_rn(v0.z, v0.w));
            u.z = h2u(__floats2half2_rn(v1.x, v1.y));
            u.w = h2u(__floats2half2_rn(v1.z, v1.w));
            ((uint4*)dst)[i] = u;
        }
    }
}

// ---------------------------------------------------------------------------
// fp16 GEMM: 128x128 CTA, 256 thr (8 warps 4x2), warp 32x64, BK=64 halves
// (one 128B row of data per smem row, stride 144), cp.async double-buffered,
// ldmatrix.x4 fragment loads. 16 chunk iterations -> half the barriers.
// ---------------------------------------------------------------------------
#define BM 128
#define BN 128
#define BK 64
#define NCH (D_ / BK)                             // 16 chunks
#define SKB 144                                   // bytes per 64-half row (128B data + 16B pad)
#define GBUF (BM * SKB)                           // 18432 B per buffer
#define GEMM_SMEM (4 * GBUF)                      // A0,A1,B0,B1 = 73,728 B

__device__ __forceinline__ void gemm_main(const __half* __restrict__ A,
                                          const __half* __restrict__ W,
                                          int m_base, int n_base,
                                          uint32_t sm_u,
                                          float acc[2][8][4])
{
    const int tid  = threadIdx.x;
    const int lane = tid & 31;
    const int warp = tid >> 5;
    const int wm = warp & 3;
    const int wn = warp >> 2;

    // ldmatrix lane->address components
    const int a_row = (lane & 7) + ((lane >> 3) & 1) * 8;
    const int a_col = ((lane >> 4) & 1) * 16;
    const int b_row = (lane & 7) + ((lane >> 4) & 1) * 8;
    const int b_col = ((lane >> 3) & 1) * 16;

    auto stage = [&](int buf, int k0) {
#pragma unroll
        for (int it = 0; it < 4; it++) {
            int id = tid + it * 256;      // 1024 16B chunks per operand
            int r  = id >> 3;
            int c  = id & 7;
            cpa16(sm_u + (uint32_t)(buf * GBUF + r * SKB + c * 16),
                  A + (size_t)(m_base + r) * D_ + k0 + c * 8);
            cpa16(sm_u + (uint32_t)(2 * GBUF + buf * GBUF + r * SKB + c * 16),
                  W + (size_t)(n_base + r) * D_ + k0 + c * 8);
        }
    };

    stage(0, 0);
    cp_commit();

    for (int ki = 0; ki < NCH; ki++) {
        const int cur = ki & 1;
        if (ki + 1 < NCH) {
            stage(cur ^ 1, (ki + 1) * BK);
            cp_commit();
            cp_wait<1>();
        } else {
            cp_wait<0>();
        }
        __syncthreads();

        const uint32_t Au = sm_u + (uint32_t)(cur * GBUF);
        const uint32_t Bu = sm_u + (uint32_t)(2 * GBUF + cur * GBUF);
#pragma unroll
        for (int kk = 0; kk < 4; kk++) {       // four k16 groups per chunk
            uint32_t af[2][4];
#pragma unroll
            for (int ma = 0; ma < 2; ma++)
                ldsm4(af[ma][0], af[ma][1], af[ma][2], af[ma][3],
                      Au + (uint32_t)((wm * 32 + ma * 16 + a_row) * SKB + a_col + kk * 32));
#pragma unroll
            for (int np = 0; np < 4; np++) {
                uint32_t b4[4];
                ldsm4(b4[0], b4[1], b4[2], b4[3],
                      Bu + (uint32_t)((wn * 64 + np * 16 + b_row) * SKB + b_col + kk * 32));
                uint32_t bf0[2] = { b4[0], b4[1] };
                uint32_t bf1[2] = { b4[2], b4[3] };
                mma16(acc[0][2 * np],     af[0], bf0);
                mma16(acc[1][2 * np],     af[1], bf0);
                mma16(acc[0][2 * np + 1], af[0], bf1);
                mma16(acc[1][2 * np + 1], af[1], bf1);
            }
        }
        __syncthreads();
    }
}

// Fused QKV. Q scaled by 0.125*log2e; V stored transposed [b,h,hd,s].
__global__ __launch_bounds__(256, 2) void qkv_gemm()
{
    extern __shared__ __align__(16) char smc[];
    uint32_t sm_u = (uint32_t)__cvta_generic_to_shared(smc);

    const int wsel = blockIdx.y >> 3;
    const __half* W = g_wh + (size_t)wsel * D_ * D_;
    __half* Cout    = (wsel == 0) ? g_Qh : (wsel == 1) ? g_Kh : g_Vh;
    const float scale = (wsel == 0) ? (0.125f * LOG2E) : 1.0f;
    const int m_base = blockIdx.x * BM;
    const int n_base = (blockIdx.y & 7) * BN;

    float acc[2][8][4];
#pragma unroll
    for (int ma = 0; ma < 2; ma++)
#pragma unroll
        for (int na = 0; na < 8; na++)
#pragma unroll
            for (int i = 0; i < 4; i++) acc[ma][na][i] = 0.f;

    gemm_main(g_xh, W, m_base, n_base, sm_u, acc);

    const int lane = threadIdx.x & 31, warp = threadIdx.x >> 5;
    const int g = lane >> 2, t4 = lane & 3;
    const int wm = warp & 3, wn = warp >> 2;
#pragma unroll
    for (int ma = 0; ma < 2; ma++)
#pragma unroll
        for (int na = 0; na < 8; na++) {
            int m0 = m_base + wm * 32 + ma * 16 + g;
            int n0 = n_base + wn * 64 + na * 8 + 2 * t4;
#pragma unroll
            for (int half_row = 0; half_row < 2; half_row++) {
                int m = m0 + half_row * 8;
                float v0 = acc[ma][na][half_row * 2 + 0] * scale;
                float v1 = acc[ma][na][half_row * 2 + 1] * scale;
                int b = m >> 11, s = m & 2047;
                int h = n0 >> 6, hd = n0 & 63;
                if (wsel == 2) {   // V transposed: [b,h,hd,s]
                    size_t base = ((size_t)(b * H_ + h) * HD_ + hd) * S_ + s;
                    g_Vh[base]      = __float2half_rn(v0);
                    g_Vh[base + S_] = __float2half_rn(v1);
                } else {
                    size_t idx = ((size_t)(b * H_ + h) * S_ + s) * HD_ + hd;
                    *(__half2*)&Cout[idx] = __floats2half2_rn(v0, v1);
                }
            }
        }
}

// Output projection: out = A @ Wo^T (fp32 output)
__global__ __launch_bounds__(256, 2) void out_gemm(float* __restrict__ out)
{
    extern __shared__ __align__(16) char smc[];
    uint32_t sm_u = (uint32_t)__cvta_generic_to_shared(smc);

    const int m_base = blockIdx.x * BM;
    const int n_base = blockIdx.y * BN;

    float acc[2][8][4];
#pragma unroll
    for (int ma = 0; ma < 2; ma++)
#pragma unroll
        for (int na = 0; na < 8; na++)
#pragma unroll
            for (int i = 0; i < 4; i++) acc[ma][na][i] = 0.f;

    gemm_main(g_Ah, g_wh + 3 * D_ * D_, m_base, n_base, sm_u, acc);

    const int lane = threadIdx.x & 31, warp = threadIdx.x >> 5;
    const int g = lane >> 2, t4 = lane & 3;
    const int wm = warp & 3, wn = warp >> 2;
#pragma unroll
    for (int ma = 0; ma < 2; ma++)
#pragma unroll
        for (int na = 0; na < 8; na++) {
            int m0 = m_base + wm * 32 + ma * 16 + g;
            int n0 = n_base + wn * 64 + na * 8 + 2 * t4;
            *(float2*)&out[(size_t)m0 * D_ + n0]       = make_float2(acc[ma][na][0], acc[ma][na][1]);
            *(float2*)&out[(size_t)(m0 + 8) * D_ + n0] = make_float2(acc[ma][na][2], acc[ma][na][3]);
        }
}

// ---------------------------------------------------------------------------
// Flash attention, fp16 mma + ldmatrix (unchanged from round 15).
// smem: Qs 18432 + Ks 2x9216 + Vt 2x9216 = 55,296 B.
// ---------------------------------------------------------------------------
#define FSB 144
#define FOFF_K (128 * FSB)
#define FOFF_V (FOFF_K + 2 * 64 * FSB)
#define FLASH_SMEM (FOFF_V + 2 * 64 * FSB)   // 55,296 B

__global__ __launch_bounds__(128, 2) void flash_mma()
{
    extern __shared__ __align__(16) char fsc[];
    const uint32_t sm_u = (uint32_t)__cvta_generic_to_shared(fsc);

    const int t = (gridDim.x - 1) - blockIdx.x;   // heavy tiles first
    const int h = blockIdx.y;
    const int b = blockIdx.z;
    const int tid  = threadIdx.x;
    const int lane = tid & 31;
    const int w    = tid >> 5;
    const int g  = lane >> 2;
    const int t4 = lane & 3;

    const int a_row = (lane & 7) + ((lane >> 3) & 1) * 8;
    const int a_col = ((lane >> 4) & 1) * 16;
    const int b_row = (lane & 7) + ((lane >> 4) & 1) * 8;
    const int b_col = ((lane >> 3) & 1) * 16;

    const __half* Qp  = g_Qh + ((size_t)(b * H_ + h) * S_ + t * 128) * HD_;
    const __half* Kp  = g_Kh + ((size_t)(b * H_ + h) * S_) * HD_;
    const __half* Vtp = g_Vh + ((size_t)(b * H_ + h)) * HD_ * S_;   // [hd][s]

#pragma unroll
    for (int it = 0; it < 8; it++) {
        int f = tid + it * 128;
        int r = f >> 3, c = (f & 7) * 16;
        cpa16(sm_u + (uint32_t)(r * FSB + c), Qp + (size_t)r * HD_ + c / 2);
    }
#pragma unroll
    for (int it = 0; it < 4; it++) {
        int f = tid + it * 128;
        int r = f >> 3, c = (f & 7) * 16;
        cpa16(sm_u + (uint32_t)(FOFF_K + r * FSB + c), Kp + (size_t)r * HD_ + c / 2);
        cpa16(sm_u + (uint32_t)(FOFF_V + r * FSB + c), Vtp + (size_t)r * S_ + c / 2);
    }
    cp_commit();

    const float slope2 = exp2f(-0.5f * (float)(h + 1)) * LOG2E;
    int qr[2][2];
#pragma unroll
    for (int rb = 0; rb < 2; rb++) {
        qr[rb][0] = t * 128 + w * 32 + rb * 16 + g;
        qr[rb][1] = qr[rb][0] + 8;
    }

    float o[2][8][4];
    float mr[2][2], lr[2][2];
#pragma unroll
    for (int rb = 0; rb < 2; rb++) {
        mr[rb][0] = mr[rb][1] = -INFINITY;
        lr[rb][0] = lr[rb][1] = 0.f;
#pragma unroll
        for (int da = 0; da < 8; da++)
#pragma unroll
            for (int i = 0; i < 4; i++) o[rb][da][i] = 0.f;
    }

    const int j_end = t * 128 + 64;
    for (int j0 = 0; j0 <= j_end; j0 += 64) {
        const int cur = (j0 >> 6) & 1;
        if (j0 + 64 <= j_end) {
            const int nb = cur ^ 1;
#pragma unroll
            for (int it = 0; it < 4; it++) {
                int f = tid + it * 128;
                int r = f >> 3, c = (f & 7) * 16;
                cpa16(sm_u + (uint32_t)(FOFF_K + (nb * 64 + r) * FSB + c),
                      Kp + (size_t)(j0 + 64 + r) * HD_ + c / 2);
                cpa16(sm_u + (uint32_t)(FOFF_V + (nb * 64 + r) * FSB + c),
                      Vtp + (size_t)r * S_ + j0 + 64 + c / 2);
            }
            cp_commit();
            cp_wait<1>();
        } else {
            cp_wait<0>();
        }
        __syncthreads();

        const uint32_t Ku = sm_u + (uint32_t)(FOFF_K + cur * 64 * FSB);
        const uint32_t Vu = sm_u + (uint32_t)(FOFF_V + cur * 64 * FSB);

        // S = Q @ K^T : 4 k16-groups over HD=64
        float s[2][8][4];
#pragma unroll
        for (int rb = 0; rb < 2; rb++)
#pragma unroll
            for (int na = 0; na < 8; na++)
#pragma unroll
                for (int i = 0; i < 4; i++) s[rb][na][i] = 0.f;

#pragma unroll
        for (int kk = 0; kk < 4; kk++) {
            uint32_t aq[2][4];
#pragma unroll
            for (int rb = 0; rb < 2; rb++)
                ldsm4(aq[rb][0], aq[rb][1], aq[rb][2], aq[rb][3],
                      sm_u + (uint32_t)((w * 32 + rb * 16 + a_row) * FSB + a_col + kk * 32));
#pragma unroll
            for (int np = 0; np < 4; np++) {
                uint32_t b4[4];
                ldsm4(b4[0], b4[1], b4[2], b4[3],
                      Ku + (uint32_t)((np * 16 + b_row) * FSB + b_col + kk * 32));
                uint32_t bf0[2] = { b4[0], b4[1] };
                uint32_t bf1[2] = { b4[2], b4[3] };
                mma16(s[0][2 * np],     aq[0], bf0);
                mma16(s[1][2 * np],     aq[1], bf0);
                mma16(s[0][2 * np + 1], aq[0], bf1);
                mma16(s[1][2 * np + 1], aq[1], bf1);
            }
        }

        // ALiBi (base-2) + causal, per row-block
#pragma unroll
        for (int rb = 0; rb < 2; rb++) {
            const bool nm = (j0 + 63) > (t * 128 + w * 32 + rb * 16);
#pragma unroll
            for (int na = 0; na < 8; na++) {
                int jc = j0 + na * 8 + 2 * t4;
                s[rb][na][0] += slope2 * (float)(jc - qr[rb][0]);
                s[rb][na][1] += slope2 * (float)(jc + 1 - qr[rb][0]);
                s[rb][na][2] += slope2 * (float)(jc - qr[rb][1]);
                s[rb][na][3] += slope2 * (float)(jc + 1 - qr[rb][1]);
                if (nm) {
                    if (jc     > qr[rb][0]) s[rb][na][0] = -1e30f;
                    if (jc + 1 > qr[rb][0]) s[rb][na][1] = -1e30f;
                    if (jc     > qr[rb][1]) s[rb][na][2] = -1e30f;
                    if (jc + 1 > qr[rb][1]) s[rb][na][3] = -1e30f;
                }
            }
        }

        // online softmax (base-2); reduce over t4 lanes
#pragma unroll
        for (int rb = 0; rb < 2; rb++) {
            float mxA = -INFINITY, mxB = -INFINITY;
#pragma unroll
            for (int na = 0; na < 8; na++) {
                mxA = fmaxf(mxA, fmaxf(s[rb][na][0], s[rb][na][1]));
                mxB = fmaxf(mxB, fmaxf(s[rb][na][2], s[rb][na][3]));
            }
            mxA = fmaxf(mxA, __shfl_xor_sync(0xffffffffu, mxA, 1));
            mxA = fmaxf(mxA, __shfl_xor_sync(0xffffffffu, mxA, 2));
            mxB = fmaxf(mxB, __shfl_xor_sync(0xffffffffu, mxB, 1));
            mxB = fmaxf(mxB, __shfl_xor_sync(0xffffffffu, mxB, 2));

            float mnA = fmaxf(mr[rb][0], mxA), mnB = fmaxf(mr[rb][1], mxB);
            float aAl = exp2f(mr[rb][0] - mnA), aBl = exp2f(mr[rb][1] - mnB);
            mr[rb][0] = mnA; mr[rb][1] = mnB;

            float sumA = 0.f, sumB = 0.f;
#pragma unroll
            for (int na = 0; na < 8; na++) {
                s[rb][na][0] = exp2f(s[rb][na][0] - mnA);
                s[rb][na][1] = exp2f(s[rb][na][1] - mnA);
                s[rb][na][2] = exp2f(s[rb][na][2] - mnB);
                s[rb][na][3] = exp2f(s[rb][na][3] - mnB);
                sumA += s[rb][na][0] + s[rb][na][1];
                sumB += s[rb][na][2] + s[rb][na][3];
            }
            sumA += __shfl_xor_sync(0xffffffffu, sumA, 1);
            sumA += __shfl_xor_sync(0xffffffffu, sumA, 2);
            sumB += __shfl_xor_sync(0xffffffffu, sumB, 1);
            sumB += __shfl_xor_sync(0xffffffffu, sumB, 2);
            lr[rb][0] = lr[rb][0] * aAl + sumA;
            lr[rb][1] = lr[rb][1] * aBl + sumB;

#pragma unroll
            for (int da = 0; da < 8; da++) {
                o[rb][da][0] *= aAl; o[rb][da][1] *= aAl;
                o[rb][da][2] *= aBl; o[rb][da][3] *= aBl;
            }
        }

        // O += P @ V : 4 k16-groups over the 64 keys. A-frags from s regs.
#pragma unroll
        for (int kk = 0; kk < 4; kk++) {
            uint32_t ap[2][4];
#pragma unroll
            for (int rb = 0; rb < 2; rb++) {
                ap[rb][0] = h2u(__floats2half2_rn(s[rb][2*kk][0],   s[rb][2*kk][1]));
                ap[rb][1] = h2u(__floats2half2_rn(s[rb][2*kk][2],   s[rb][2*kk][3]));
                ap[rb][2] = h2u(__floats2half2_rn(s[rb][2*kk+1][0], s[rb][2*kk+1][1]));
                ap[rb][3] = h2u(__floats2half2_rn(s[rb][2*kk+1][2], s[rb][2*kk+1][3]));
            }
#pragma unroll
            for (int np = 0; np < 4; np++) {
                uint32_t b4[4];
                ldsm4(b4[0], b4[1], b4[2], b4[3],
                      Vu + (uint32_t)((np * 16 + b_row) * FSB + b_col + kk * 32));
                uint32_t bf0[2] = { b4[0], b4[1] };
                uint32_t bf1[2] = { b4[2], b4[3] };
                mma16(o[0][2 * np],     ap[0], bf0);
                mma16(o[1][2 * np],     ap[1], bf0);
                mma16(o[0][2 * np + 1], ap[0], bf1);
                mma16(o[1][2 * np + 1], ap[1], bf1);
            }
        }
        __syncthreads();
    }

    // normalize + write [B,S,D] as fp16 (input to out_gemm)
#pragma unroll
    for (int rb = 0; rb < 2; rb++) {
        const float invA = 1.0f / lr[rb][0], invB = 1.0f / lr[rb][1];
#pragma unroll
        for (int da = 0; da < 8; da++) {
            int col = h * 64 + da * 8 + 2 * t4;
            size_t rA = ((size_t)b * S_ + qr[rb][0]) * D_ + col;
            size_t rB = ((size_t)b * S_ + qr[rb][1]) * D_ + col;
            *(__half2*)&g_Ah[rA] = __floats2half2_rn(o[rb][da][0] * invA, o[rb][da][1] * invA);
            *(__half2*)&g_Ah[rB] = __floats2half2_rn(o[rb][da][2] * invB, o[rb][da][3] * invB);
        }
    }
}

// ---------------------------------------------------------------------------
extern "C" void kernel_launch(void* const* d_in, const int* in_sizes, int n_in,
                              void* d_out, int out_size)
{
    const float* x  = (const float*)d_in[0];
    // d_in[1] = causal mask, applied analytically
    const float* Wq = (const float*)d_in[2];
    const float* Wk = (const float*)d_in[3];
    const float* Wv = (const float*)d_in[4];
    const float* Wo = (const float*)d_in[5];
    float* out = (float*)d_out;

    cudaFuncSetAttribute(qkv_gemm, cudaFuncAttributeMaxDynamicSharedMemorySize, (int)GEMM_SMEM);
    cudaFuncSetAttribute(out_gemm, cudaFuncAttributeMaxDynamicSharedMemorySize, (int)GEMM_SMEM);
    cudaFuncSetAttribute(flash_mma, cudaFuncAttributeMaxDynamicSharedMemorySize, (int)FLASH_SMEM);

    dim3 g0(1024, 5);
    precvt<<<g0, 256>>>(x, Wq, Wk, Wv, Wo);

    dim3 g1(M_ / BM, 24);                 // 3 weights x 8 n-tiles
    qkv_gemm<<<g1, 256, GEMM_SMEM>>>();

    dim3 g2(S_ / 128, H_, B_);
    flash_mma<<<g2, 128, FLASH_SMEM>>>();

    dim3 g3(M_ / BM, D_ / BN);
    out_gemm<<<g3, 256, GEMM_SMEM>>>(out);
}